// round 9
// baseline (speedup 1.0000x reference)
#include <cuda_runtime.h>
#include <cstdint>
#include <cstddef>

#define BATCH   4096
#define FFI     64
#define DDIM    256
#define PAIRS   2016
#define THREADS 128
#define KC      64            // K elements per chunk
#define NCH     (DDIM / KC)   // 4
#define SROW    72            // padded smem row stride (words), ==8 mod 32
#define NCTA    1024
#define BPC     (BATCH / NCTA) // 4 batches per persistent CTA

// Minimal-union tile->warp assignment: 20 upper-triangular m16n8 tiles.
//  w0: strip0 x nj{0..4}            groups {0,1,2,3,4}
//  w1: strip0 x nj{5,6,7} + strip3 x nj{6,7}   groups {0,1,5,6,7}
//  w2: strip1 x nj{2..7}            groups {2,3,4,5,6,7}
//  w3: strip2 x nj{4..7}            groups {4,5,6,7}
// total group-loads per ks = 5+5+6+4 = 20 (theoretical minimum).
// cAI = index of A-group pair start within the warp's group list (pairs are
// adjacent in the list); cBI = index of B group. B frags alias A raw words.
__device__ constexpr int cNT[4]     = {5, 5, 6, 4};   // tiles per warp
__device__ constexpr int cNG[4]     = {5, 5, 6, 4};   // groups per warp
__device__ constexpr int cGRP[4][6] = {{0,1,2,3,4,0},{0,1,5,6,7,0},
                                       {2,3,4,5,6,7},{4,5,6,7,0,0}};
__device__ constexpr int cAI[4][6]  = {{0,0,0,0,0,0},{0,0,0,3,3,0},
                                       {0,0,0,0,0,0},{0,0,0,0,0,0}};
__device__ constexpr int cBI[4][6]  = {{0,1,2,3,4,0},{2,3,4,3,4,0},
                                       {0,1,2,3,4,5},{0,1,2,3,0,0}};
__device__ constexpr int cMI[4][6]  = {{0,0,0,0,0,0},{0,0,0,3,3,0},
                                       {1,1,1,1,1,1},{2,2,2,2,0,0}};
__device__ constexpr int cNJ[4][6]  = {{0,1,2,3,4,0},{5,6,7,6,7,0},
                                       {2,3,4,5,6,7},{4,5,6,7,0,0}};

__device__ __forceinline__ uint32_t f2tf32(float x) {
    uint32_t r;
    asm("cvt.rna.tf32.f32 %0, %1;" : "=r"(r) : "f"(x));
    return r;
}

__device__ __forceinline__ void mma8(float& d0, float& d1, float& d2, float& d3,
                                     uint32_t a0, uint32_t a1, uint32_t a2, uint32_t a3,
                                     uint32_t b0, uint32_t b1) {
    asm("mma.sync.aligned.m16n8k8.row.col.f32.tf32.tf32.f32 "
        "{%0,%1,%2,%3}, {%4,%5,%6,%7}, {%8,%9}, {%0,%1,%2,%3};"
        : "+f"(d0), "+f"(d1), "+f"(d2), "+f"(d3)
        : "r"(a0), "r"(a1), "r"(a2), "r"(a3), "r"(b0), "r"(b1));
}

// k-permutation trick (see R7): lane k-slots (2q, 2q+1) instead of (q, q+4);
// valid because A and B fragments alias the SAME smem words with the SAME
// permutation, so the accumulated sum over k is unchanged.
template <int W>
__device__ __forceinline__ void chunk_mma(const uint32_t* __restrict__ sb,
                                          int lid, float (&acc)[24]) {
    const int grp = lid >> 2, quad = lid & 3;
    const uint32_t* base = sb + grp * SROW + 2 * quad;
#pragma unroll
    for (int ks = 0; ks < KC / 8; ks++) {
        const int k = ks * 8;
        uint32_t c[6][2];
#pragma unroll
        for (int gi = 0; gi < cNG[W]; gi++) {
            const int g = cGRP[W][gi];
            uint2 v = *reinterpret_cast<const uint2*>(base + g * 8 * SROW + k);
            c[gi][0] = v.x; c[gi][1] = v.y;
        }
#pragma unroll
        for (int t = 0; t < cNT[W]; t++) {
            const int a = cAI[W][t], bj = cBI[W][t];
            mma8(acc[4 * t], acc[4 * t + 1], acc[4 * t + 2], acc[4 * t + 3],
                 c[a][0], c[a + 1][0], c[a][1], c[a + 1][1],
                 c[bj][0], c[bj][1]);
        }
    }
}

__device__ __forceinline__ void stp(float* __restrict__ ob, int i, int j,
                                    float v, bool need_check) {
    if (!need_check || j > i)
        ob[i * FFI - (i * (i + 1)) / 2 + j - i - 1] = v;
}

template <int W>
__device__ __forceinline__ void epilogue(const float (&acc)[24], int lid,
                                         float* __restrict__ ob) {
    const int grp = lid >> 2, quad = lid & 3;
#pragma unroll
    for (int t = 0; t < cNT[W]; t++) {
        const int mi = cMI[W][t];
        const int nj = cNJ[W][t];
        const bool chk = (nj < 2 * mi + 2);   // tile straddles the diagonal
        const int i0 = mi * 16 + grp, i1 = i0 + 8;
        const int j0 = nj * 8 + 2 * quad, j1 = j0 + 1;
        stp(ob, i0, j0, acc[4 * t + 0], chk);
        stp(ob, i0, j1, acc[4 * t + 1], chk);
        stp(ob, i1, j0, acc[4 * t + 2], chk);
        stp(ob, i1, j1, acc[4 * t + 3], chk);
    }
}

__global__ void __launch_bounds__(THREADS, 5)
gram_mma_kernel(const float* __restrict__ in, float* __restrict__ out) {
    __shared__ __align__(16) uint32_t sb[2][FFI * SROW];   // 36864 B

    const int tid = threadIdx.x;
    const int wid = tid >> 5, lid = tid & 31;

    const int lrow = tid >> 4;      // 0..7 row-within-group-of-8
    const int lcol = tid & 15;      // float4 column within chunk

    float4 regs[8];
    auto load_chunk = [&](const float4* __restrict__ src, int c) {
#pragma unroll
        for (int i = 0; i < 8; i++) {
            const int r = i * 8 + lrow;
            regs[i] = __ldg(src + (size_t)r * (DDIM / 4) + c * (KC / 4) + lcol);
        }
    };
    auto store_chunk = [&](int buf) {
#pragma unroll
        for (int i = 0; i < 8; i++) {
            const int r = i * 8 + lrow;
            uint4 v;
            v.x = f2tf32(regs[i].x); v.y = f2tf32(regs[i].y);
            v.z = f2tf32(regs[i].z); v.w = f2tf32(regs[i].w);
            *reinterpret_cast<uint4*>(&sb[buf][r * SROW + lcol * 4]) = v;
        }
    };

    // persistent over BPC consecutive batches; the chunk-3 prefetch slot
    // loads chunk 0 of the NEXT batch so the LDG stream never stalls.
    const size_t b0 = (size_t)blockIdx.x * BPC;
    const float4* src = reinterpret_cast<const float4*>(in)
                        + b0 * FFI * (DDIM / 4);
    load_chunk(src, 0);

    for (int it = 0; it < BPC; it++) {
        float acc[24];
#pragma unroll
        for (int i = 0; i < 24; i++) acc[i] = 0.0f;

        const float4* srcn = src + FFI * (DDIM / 4);   // next batch

        for (int c = 0; c < NCH; c++) {
            store_chunk(c & 1);
            __syncthreads();
            if (c + 1 < NCH)           load_chunk(src, c + 1);
            else if (it + 1 < BPC)     load_chunk(srcn, 0);
            const uint32_t* buf = sb[c & 1];
            switch (wid) {
                case 0:  chunk_mma<0>(buf, lid, acc); break;
                case 1:  chunk_mma<1>(buf, lid, acc); break;
                case 2:  chunk_mma<2>(buf, lid, acc); break;
                default: chunk_mma<3>(buf, lid, acc); break;
            }
            // no trailing barrier: writer of a buffer is two barriers past
            // its last reader (see per-warp ordering argument).
        }

        float* ob = out + (b0 + it) * PAIRS;
        switch (wid) {
            case 0:  epilogue<0>(acc, lid, ob); break;
            case 1:  epilogue<1>(acc, lid, ob); break;
            case 2:  epilogue<2>(acc, lid, ob); break;
            default: epilogue<3>(acc, lid, ob); break;
        }
        src = srcn;
    }
}

extern "C" void kernel_launch(void* const* d_in, const int* in_sizes, int n_in,
                              void* d_out, int out_size) {
    const float* in = (const float*)d_in[0];
    float* out = (float*)d_out;
    (void)in_sizes; (void)n_in; (void)out_size;
    gram_mma_kernel<<<NCTA, THREADS>>>(in, out);
}